// round 1
// baseline (speedup 1.0000x reference)
#include <cuda_runtime.h>
#include <math.h>
#include <stdint.h>

// Problem constants
#define L_ 4
#define B_ 2
#define N_ 1024
#define D_ 1024
#define H_ 16
#define V_ 32000
#define M_ 2048
#define DH_ 64
#define FF_ 4096
#define MN_ 3072   // M + N
#define SCALE_ 0.125f  // DH^-0.5

// ---------------------------------------------------------------------------
// Scratch (device globals; no allocation allowed)
// ---------------------------------------------------------------------------
__device__ __align__(16) float g_h   [(size_t)B_*N_*D_];
__device__ __align__(16) float g_xn  [(size_t)B_*N_*D_];
__device__ __align__(16) float g_q   [(size_t)B_*N_*D_];
__device__ __align__(16) float g_ao  [(size_t)B_*N_*D_];
__device__ __align__(16) float g_kv  [(size_t)B_*MN_*2*D_];
__device__ __align__(16) float g_pe  [(size_t)N_*D_];
__device__ __align__(16) float g_pos [(size_t)N_*DH_];
__device__ __align__(16) float g_qpos[(size_t)B_*H_*N_*N_];
__device__ __align__(16) float g_dots[(size_t)B_*H_*N_*MN_];
__device__ __align__(16) float g_f1  [(size_t)B_*N_*FF_];
__device__ __align__(16) float g_emask[(size_t)B_*MN_];
__device__ __align__(16) float g_auxbuf[(size_t)B_*M_];
__device__ float g_aux[1];

// ---------------------------------------------------------------------------
// Generic batched SGEMM: C[z] = A[z] @ B[z] (+bias) with epilogues.
// Batch index z decomposes as (zo = z/Hdiv, zi = z%Hdiv) for (batch, head).
// EPI: 0 = bias, 1 = bias + residual, 2 = bias + exact GELU,
//      3 = attention scores: scale, rel-shift positional gather, causal mask.
// BM=BN=128, BK=8, 256 threads, 8x8 per thread.
// Requirements: K % 8 == 0, all pointers/lds 16B-aligned (true for all calls).
// ---------------------------------------------------------------------------
template<bool TRANSB, int EPI>
__global__ void __launch_bounds__(256)
gemm_kernel(const float* __restrict__ A, int lda, long long sAo, long long sAi,
            const float* __restrict__ B, int ldb, long long sBo, long long sBi,
            const float* __restrict__ bias,
            float* __restrict__ C, int ldc, long long sCo, long long sCi,
            const float* __restrict__ res, int ldr,
            int Mrows, int Ncols, int K, int Hdiv,
            float scale, const float* __restrict__ qpos, long long sQ,
            int Mctx, int qposN)
{
    const int z = blockIdx.z;
    const int zo = z / Hdiv, zi = z % Hdiv;
    A += (long long)zo * sAo + (long long)zi * sAi;
    B += (long long)zo * sBo + (long long)zi * sBi;
    C += (long long)zo * sCo + (long long)zi * sCi;
    const float* qp = (EPI == 3) ? (qpos + (long long)z * sQ) : nullptr;

    __shared__ float As[8][128];
    __shared__ float Bs[8][128];

    const int tid = threadIdx.x;
    const int tx = tid & 15, ty = tid >> 4;
    const int r0 = blockIdx.y * 128;
    const int c0 = blockIdx.x * 128;

    float acc[8][8];
    #pragma unroll
    for (int i = 0; i < 8; i++)
        #pragma unroll
        for (int j = 0; j < 8; j++) acc[i][j] = 0.f;

    const int am = tid >> 1;          // A: row within tile
    const int ak = (tid & 1) * 4;     // A: k within tile (float4)

    for (int k0 = 0; k0 < K; k0 += 8) {
        // Load A tile (128 x 8), stored k-major
        {
            float4 v = make_float4(0.f, 0.f, 0.f, 0.f);
            int gm = r0 + am;
            if (gm < Mrows)
                v = *reinterpret_cast<const float4*>(A + (long long)gm * lda + k0 + ak);
            As[ak + 0][am] = v.x; As[ak + 1][am] = v.y;
            As[ak + 2][am] = v.z; As[ak + 3][am] = v.w;
        }
        // Load B tile (8 x 128)
        if (!TRANSB) {
            int kk = tid >> 5;
            int c  = (tid & 31) * 4;
            float4 v = make_float4(0.f, 0.f, 0.f, 0.f);
            int gc = c0 + c;
            if (gc < Ncols)
                v = *reinterpret_cast<const float4*>(B + (long long)(k0 + kk) * ldb + gc);
            Bs[kk][c + 0] = v.x; Bs[kk][c + 1] = v.y;
            Bs[kk][c + 2] = v.z; Bs[kk][c + 3] = v.w;
        } else {
            int c  = tid >> 1;
            int kk = (tid & 1) * 4;
            float4 v = make_float4(0.f, 0.f, 0.f, 0.f);
            int gc = c0 + c;
            if (gc < Ncols)
                v = *reinterpret_cast<const float4*>(B + (long long)gc * ldb + k0 + kk);
            Bs[kk + 0][c] = v.x; Bs[kk + 1][c] = v.y;
            Bs[kk + 2][c] = v.z; Bs[kk + 3][c] = v.w;
        }
        __syncthreads();

        #pragma unroll
        for (int kk = 0; kk < 8; kk++) {
            float a[8], b[8];
            #pragma unroll
            for (int i = 0; i < 8; i++) a[i] = As[kk][ty * 8 + i];
            #pragma unroll
            for (int j = 0; j < 8; j++) b[j] = Bs[kk][tx * 8 + j];
            #pragma unroll
            for (int i = 0; i < 8; i++)
                #pragma unroll
                for (int j = 0; j < 8; j++)
                    acc[i][j] = fmaf(a[i], b[j], acc[i][j]);
        }
        __syncthreads();
    }

    // Epilogue
    #pragma unroll
    for (int i = 0; i < 8; i++) {
        int r = r0 + ty * 8 + i;
        if (r >= Mrows) continue;
        #pragma unroll
        for (int j = 0; j < 8; j++) {
            int c = c0 + tx * 8 + j;
            if (c >= Ncols) continue;
            float v = acc[i][j];
            if (EPI == 3) {
                v *= scale;
                if (c > Mctx + r) {
                    v = -1e30f;                       // causal mask
                } else if (c >= Mctx) {
                    // rel-shifted positional term: pos row = qposN-1-r + (c-Mctx)
                    v += scale * qp[(long long)r * qposN + (qposN - 1 - r + c - Mctx)];
                }
            } else {
                if (bias) v += bias[c];
                if (EPI == 1) v += res[(long long)r * ldr + c];
                if (EPI == 2) v = 0.5f * v * (1.0f + erff(v * 0.70710678118654752f));
            }
            C[(long long)r * ldc + c] = v;
        }
    }
}

// ---------------------------------------------------------------------------
// Small kernels
// ---------------------------------------------------------------------------
__global__ void pe_kernel(float* __restrict__ pe)
{
    int jj = blockIdx.x;
    double t = (double)(N_ - 1 - jj);
    for (int m = threadIdx.x; m < D_ / 2; m += blockDim.x) {
        double inv = exp(-((2.0 * m) / (double)D_) * log(10000.0));
        double a = t * inv;
        pe[(size_t)jj * D_ + m]            = (float)sin(a);
        pe[(size_t)jj * D_ + D_ / 2 + m]   = (float)cos(a);
    }
}

__global__ void init_aux_kernel() { g_aux[0] = 0.0f; }

__global__ void embed_kernel(const int* __restrict__ x,
                             const float* __restrict__ emb,
                             float* __restrict__ h)
{
    int idx = blockIdx.x;                 // b*N + n
    int tok = x[idx];
    const float* src = emb + (size_t)tok * D_;
    float* dst = h + (size_t)idx * D_;
    for (int i = threadIdx.x; i < D_; i += blockDim.x) dst[i] = src[i];
}

__global__ void layernorm_kernel(const float* __restrict__ in,
                                 const float* __restrict__ g,
                                 const float* __restrict__ bb,
                                 float* __restrict__ out)
{
    size_t row = blockIdx.x;
    const float* p = in + row * D_;
    float s = 0.f, s2 = 0.f;
    for (int i = threadIdx.x; i < D_; i += 256) { float v = p[i]; s += v; s2 += v * v; }
    __shared__ float sh1[256], sh2[256];
    sh1[threadIdx.x] = s; sh2[threadIdx.x] = s2;
    __syncthreads();
    for (int o = 128; o > 0; o >>= 1) {
        if (threadIdx.x < o) { sh1[threadIdx.x] += sh1[threadIdx.x + o];
                               sh2[threadIdx.x] += sh2[threadIdx.x + o]; }
        __syncthreads();
    }
    float mu  = sh1[0] * (1.0f / D_);
    float var = sh2[0] * (1.0f / D_) - mu * mu;
    float inv = rsqrtf(var + 1e-5f);
    for (int i = threadIdx.x; i < D_; i += 256)
        out[row * D_ + i] = (p[i] - mu) * inv * g[i] + bb[i];
}

// exps + emask + aux candidates for one layer
__global__ void expire_kernel(const float* __restrict__ mem,     // (B, M, D)
                              const int*   __restrict__ times,   // (B, M)
                              const float* __restrict__ Wexp,    // (D,)
                              const float* __restrict__ bexp)    // scalar
{
    int j = blockIdx.x;
    int b = blockIdx.y;
    if (j >= M_) {
        if (threadIdx.x == 0) g_emask[(size_t)b * MN_ + j] = 1.0f;
        return;
    }
    const float* row = mem + ((size_t)b * M_ + j) * D_;
    float s = 0.f;
    for (int i = threadIdx.x; i < D_; i += 256) s += row[i] * Wexp[i];
    __shared__ float sh[256];
    sh[threadIdx.x] = s;
    __syncthreads();
    for (int o = 128; o > 0; o >>= 1) {
        if (threadIdx.x < o) sh[threadIdx.x] += sh[threadIdx.x + o];
        __syncthreads();
    }
    if (threadIdx.x == 0) {
        float e  = (1.0f / (1.0f + expf(-(sh[0] + bexp[0])))) * 2048.0f;
        float r  = e - (float)times[(size_t)b * M_ + j];
        float em = fminf(fmaxf(r * (1.0f / 128.0f) + 1.0f, 0.0f), 1.0f);
        g_emask[(size_t)b * MN_ + j] = em;
        g_auxbuf[(size_t)b * M_ + j] = (em > 0.0f && em < 1.0f) ? e : 0.0f;
    }
}

// Deterministic fixed-order reduction of aux candidates
__global__ void aux_reduce_kernel()
{
    float s = 0.f;
    for (int i = threadIdx.x; i < B_ * M_; i += 256) s += g_auxbuf[i];
    __shared__ float sh[256];
    sh[threadIdx.x] = s;
    __syncthreads();
    for (int o = 128; o > 0; o >>= 1) {
        if (threadIdx.x < o) sh[threadIdx.x] += sh[threadIdx.x + o];
        __syncthreads();
    }
    if (threadIdx.x == 0) g_aux[0] += sh[0] * (1.0f / 1024.0f) * 1e-6f;
}

// Row softmax over MN_ entries, then post-softmax emask multiply
__global__ void softmax_kernel()
{
    size_t row = blockIdx.x;                 // (b*H + h)*N + i
    int b = (int)(row / ((size_t)H_ * N_));
    float* p = g_dots + row * (size_t)MN_;
    const float* em = g_emask + (size_t)b * MN_;
    __shared__ float sh[256];

    float m = -1e30f;
    for (int j = threadIdx.x; j < MN_; j += 256) m = fmaxf(m, p[j]);
    sh[threadIdx.x] = m;
    __syncthreads();
    for (int o = 128; o > 0; o >>= 1) {
        if (threadIdx.x < o) sh[threadIdx.x] = fmaxf(sh[threadIdx.x], sh[threadIdx.x + o]);
        __syncthreads();
    }
    m = sh[0];
    __syncthreads();

    float s = 0.f;
    for (int j = threadIdx.x; j < MN_; j += 256) s += expf(p[j] - m);
    sh[threadIdx.x] = s;
    __syncthreads();
    for (int o = 128; o > 0; o >>= 1) {
        if (threadIdx.x < o) sh[threadIdx.x] += sh[threadIdx.x + o];
        __syncthreads();
    }
    float inv = 1.0f / sh[0];
    for (int j = threadIdx.x; j < MN_; j += 256)
        p[j] = expf(p[j] - m) * inv * em[j];
}

__global__ void write_aux_kernel(float* __restrict__ out, int out_size)
{
    const long long nlog = (long long)B_ * N_ * V_;
    if (out_size > nlog) out[nlog] = g_aux[0];
}

// ---------------------------------------------------------------------------
// Host orchestration
// ---------------------------------------------------------------------------
static inline dim3 gemm_grid(int Mrows, int Ncols, int z)
{
    return dim3((Ncols + 127) / 128, (Mrows + 127) / 128, z);
}

extern "C" void kernel_launch(void* const* d_in, const int* in_sizes, int n_in,
                              void* d_out, int out_size)
{
    const int*   x    = (const int*)  d_in[0];
    const float* mems = (const float*)d_in[1];
    const int*   times= (const int*)  d_in[2];
    const float* emb  = (const float*)d_in[3];
    const float* Wq   = (const float*)d_in[4];
    const float* bq   = (const float*)d_in[5];
    const float* Wkv  = (const float*)d_in[6];
    const float* bkv  = (const float*)d_in[7];
    const float* Wo   = (const float*)d_in[8];
    const float* bo   = (const float*)d_in[9];
    const float* Wpos = (const float*)d_in[10];
    const float* bpos = (const float*)d_in[11];
    const float* Wexp = (const float*)d_in[12];
    const float* bexp = (const float*)d_in[13];
    const float* ln1g = (const float*)d_in[14];
    const float* ln1b = (const float*)d_in[15];
    const float* ln2g = (const float*)d_in[16];
    const float* ln2b = (const float*)d_in[17];
    const float* Wff1 = (const float*)d_in[18];
    const float* bff1 = (const float*)d_in[19];
    const float* Wff2 = (const float*)d_in[20];
    const float* bff2 = (const float*)d_in[21];
    const float* Wlog = (const float*)d_in[22];
    const float* blog = (const float*)d_in[23];
    float* out = (float*)d_out;

    float *h, *xn, *q, *ao, *kv, *pe, *pos, *qpos, *dots, *f1;
    cudaGetSymbolAddress((void**)&h,    g_h);
    cudaGetSymbolAddress((void**)&xn,   g_xn);
    cudaGetSymbolAddress((void**)&q,    g_q);
    cudaGetSymbolAddress((void**)&ao,   g_ao);
    cudaGetSymbolAddress((void**)&kv,   g_kv);
    cudaGetSymbolAddress((void**)&pe,   g_pe);
    cudaGetSymbolAddress((void**)&pos,  g_pos);
    cudaGetSymbolAddress((void**)&qpos, g_qpos);
    cudaGetSymbolAddress((void**)&dots, g_dots);
    cudaGetSymbolAddress((void**)&f1,   g_f1);

    pe_kernel<<<N_, 512>>>(pe);
    init_aux_kernel<<<1, 1>>>();
    embed_kernel<<<B_ * N_, 256>>>(x, emb, h);

    const long long sKVb = (long long)MN_ * 2 * D_;   // kv batch stride
    const long long sDb  = (long long)H_ * N_ * MN_;  // dots batch(b) stride
    const long long sDh  = (long long)N_ * MN_;       // dots head stride

    for (int l = 0; l < L_; l++) {
        // --- expiration mask + aux ---
        expire_kernel<<<dim3(MN_, B_), 256>>>(mems + (size_t)l * B_ * M_ * D_,
                                              times + (size_t)l * B_ * M_,
                                              Wexp + (size_t)l * D_,
                                              bexp + l);
        aux_reduce_kernel<<<1, 256>>>();

        // --- xn = LN1(h) ---
        layernorm_kernel<<<B_ * N_, 256>>>(h, ln1g + (size_t)l * D_, ln1b + (size_t)l * D_, xn);

        // --- q = xn @ Wq + bq  (2048 x 1024, K=1024) ---
        gemm_kernel<false, 0><<<gemm_grid(B_ * N_, D_, 1), 256>>>(
            xn, D_, 0, 0, Wq + (size_t)l * D_ * D_, D_, 0, 0, bq + (size_t)l * D_,
            q, D_, 0, 0, nullptr, 0, B_ * N_, D_, D_, 1, 0.f, nullptr, 0, 0, 0);

        // --- kv[:, :M] = mem @ Wkv + bkv  (per batch) ---
        gemm_kernel<false, 0><<<gemm_grid(M_, 2 * D_, B_), 256>>>(
            mems + (size_t)l * B_ * M_ * D_, D_, (long long)M_ * D_, 0,
            Wkv + (size_t)l * D_ * 2 * D_, 2 * D_, 0, 0, bkv + (size_t)l * 2 * D_,
            kv, 2 * D_, sKVb, 0, nullptr, 0, M_, 2 * D_, D_, 1, 0.f, nullptr, 0, 0, 0);

        // --- kv[:, M:] = xn @ Wkv + bkv  (per batch) ---
        gemm_kernel<false, 0><<<gemm_grid(N_, 2 * D_, B_), 256>>>(
            xn, D_, (long long)N_ * D_, 0,
            Wkv + (size_t)l * D_ * 2 * D_, 2 * D_, 0, 0, bkv + (size_t)l * 2 * D_,
            kv + (size_t)M_ * 2 * D_, 2 * D_, sKVb, 0, nullptr, 0,
            N_, 2 * D_, D_, 1, 0.f, nullptr, 0, 0, 0);

        // --- pos = pe @ Wpos + bpos  (1024 x 64, K=1024) ---
        gemm_kernel<false, 0><<<gemm_grid(N_, DH_, 1), 256>>>(
            pe, D_, 0, 0, Wpos + (size_t)l * D_ * DH_, DH_, 0, 0, bpos + (size_t)l * DH_,
            pos, DH_, 0, 0, nullptr, 0, N_, DH_, D_, 1, 0.f, nullptr, 0, 0, 0);

        // --- qpos[b,h] = q[b,:,h,:] @ pos^T  (1024 x 1024, K=64), 32 batches ---
        gemm_kernel<true, 0><<<gemm_grid(N_, N_, B_ * H_), 256>>>(
            q, D_, (long long)N_ * D_, DH_,
            pos, DH_, 0, 0, nullptr,
            qpos, N_, (long long)H_ * N_ * N_, (long long)N_ * N_, nullptr, 0,
            N_, N_, DH_, H_, 0.f, nullptr, 0, 0, 0);

        // --- dots = SCALE*(q k^T) + rel-shift(pos) + causal mask ---
        gemm_kernel<true, 3><<<gemm_grid(N_, MN_, B_ * H_), 256>>>(
            q, D_, (long long)N_ * D_, DH_,
            kv, 2 * D_, sKVb, DH_, nullptr,
            dots, MN_, sDb, sDh, nullptr, 0,
            N_, MN_, DH_, H_, SCALE_, qpos, (long long)N_ * N_, M_, N_);

        // --- softmax rows, post-multiply emask ---
        softmax_kernel<<<B_ * H_ * N_, 256>>>();

        // --- ao[b,:,h,:] = attn @ v  (1024 x 64, K=3072), 32 batches ---
        gemm_kernel<false, 0><<<gemm_grid(N_, DH_, B_ * H_), 256>>>(
            dots, MN_, sDb, sDh,
            kv + D_, 2 * D_, sKVb, DH_, nullptr,
            ao, D_, (long long)N_ * D_, DH_, nullptr, 0,
            N_, DH_, MN_, H_, 0.f, nullptr, 0, 0, 0);

        // --- h = ao @ Wo + bo + h ---
        gemm_kernel<false, 1><<<gemm_grid(B_ * N_, D_, 1), 256>>>(
            ao, D_, 0, 0, Wo + (size_t)l * D_ * D_, D_, 0, 0, bo + (size_t)l * D_,
            h, D_, 0, 0, h, D_, B_ * N_, D_, D_, 1, 0.f, nullptr, 0, 0, 0);

        // --- xn = LN2(h) ---
        layernorm_kernel<<<B_ * N_, 256>>>(h, ln2g + (size_t)l * D_, ln2b + (size_t)l * D_, xn);

        // --- f1 = gelu(xn @ Wff1 + bff1)  (2048 x 4096, K=1024) ---
        gemm_kernel<false, 2><<<gemm_grid(B_ * N_, FF_, 1), 256>>>(
            xn, D_, 0, 0, Wff1 + (size_t)l * D_ * FF_, FF_, 0, 0, bff1 + (size_t)l * FF_,
            f1, FF_, 0, 0, nullptr, 0, B_ * N_, FF_, D_, 1, 0.f, nullptr, 0, 0, 0);

        // --- h = f1 @ Wff2 + bff2 + h  (2048 x 1024, K=4096) ---
        gemm_kernel<false, 1><<<gemm_grid(B_ * N_, D_, 1), 256>>>(
            f1, FF_, 0, 0, Wff2 + (size_t)l * FF_ * D_, D_, 0, 0, bff2 + (size_t)l * D_,
            h, D_, 0, 0, h, D_, B_ * N_, D_, FF_, 1, 0.f, nullptr, 0, 0, 0);
    }

    // --- logits = h @ Wlog + blog  (2048 x 32000, K=1024) -> d_out ---
    gemm_kernel<false, 0><<<gemm_grid(B_ * N_, V_, 1), 256>>>(
        h, D_, 0, 0, Wlog, V_, 0, 0, blog,
        out, V_, 0, 0, nullptr, 0, B_ * N_, V_, D_, 1, 0.f, nullptr, 0, 0, 0);

    write_aux_kernel<<<1, 1>>>(out, out_size);
}

// round 2
// speedup vs baseline: 2.4704x; 2.4704x over previous
#include <cuda_runtime.h>
#include <math.h>
#include <stdint.h>

// Problem constants
#define L_ 4
#define B_ 2
#define N_ 1024
#define D_ 1024
#define H_ 16
#define V_ 32000
#define M_ 2048
#define DH_ 64
#define FF_ 4096
#define MN_ 3072   // M + N
#define SCALE_ 0.125f  // DH^-0.5

// ---------------------------------------------------------------------------
// Scratch (device globals; no allocation allowed)
// ---------------------------------------------------------------------------
__device__ __align__(16) float g_h   [(size_t)B_*N_*D_];
__device__ __align__(16) float g_xn  [(size_t)B_*N_*D_];
__device__ __align__(16) float g_q   [(size_t)B_*N_*D_];
__device__ __align__(16) float g_ao  [(size_t)B_*N_*D_];
__device__ __align__(16) float g_kv  [(size_t)B_*MN_*2*D_];
__device__ __align__(16) float g_pe  [(size_t)N_*D_];
__device__ __align__(16) float g_pos [(size_t)N_*DH_];
__device__ __align__(16) float g_qpos[(size_t)B_*H_*N_*N_];
__device__ __align__(16) float g_dots[(size_t)B_*H_*N_*MN_];
__device__ __align__(16) float g_f1  [(size_t)B_*N_*FF_];
__device__ __align__(16) float g_emask[(size_t)B_*MN_];
__device__ __align__(16) float g_auxbuf[(size_t)B_*M_];
__device__ float g_aux[1];

// ---------------------------------------------------------------------------
// bf16x3 helpers
// ---------------------------------------------------------------------------
__device__ __forceinline__ uint32_t pack_hi(float x, float y)
{
    // truncated bf16 of x in low half, of y in high half
    return __byte_perm(__float_as_uint(x), __float_as_uint(y), 0x7632);
}
__device__ __forceinline__ uint32_t pack_lo(float x, float y)
{
    float hx = __uint_as_float(__float_as_uint(x) & 0xFFFF0000u);
    float hy = __uint_as_float(__float_as_uint(y) & 0xFFFF0000u);
    uint32_t r;
    // d = { cvt(first src) in HIGH half, cvt(second src) in LOW half }
    asm("cvt.rn.bf16x2.f32 %0, %1, %2;" : "=r"(r) : "f"(y - hy), "f"(x - hx));
    return r;
}
__device__ __forceinline__ void split_pair(float x, float y,
                                           uint32_t& hi, uint32_t& lo)
{
    hi = pack_hi(x, y);
    lo = pack_lo(x, y);
}
__device__ __forceinline__ void mma_bf16(float c[4],
                                         uint32_t a0, uint32_t a1,
                                         uint32_t a2, uint32_t a3,
                                         uint32_t b0, uint32_t b1)
{
    asm volatile(
        "mma.sync.aligned.m16n8k16.row.col.f32.bf16.bf16.f32 "
        "{%0,%1,%2,%3},{%4,%5,%6,%7},{%8,%9},{%0,%1,%2,%3};"
        : "+f"(c[0]), "+f"(c[1]), "+f"(c[2]), "+f"(c[3])
        : "r"(a0), "r"(a1), "r"(a2), "r"(a3), "r"(b0), "r"(b1));
}

// ---------------------------------------------------------------------------
// Tensor-core batched GEMM: C[z] = A[z] @ B[z] (+bias) with epilogues.
// fp32 in/out; internally bf16_hi/bf16_lo 3-term mma (rel err ~1e-5).
// Batch index z decomposes as (zo=z/Hdiv, zi=z%Hdiv).
// EPI: 0 = bias, 1 = bias + residual, 2 = bias + exact GELU,
//      3 = attention scores: scale, rel-shift positional gather, causal mask.
// BM=128, BN in {128,64}, BK=16, 256 threads (8 warps, 2m x 4n).
// Requires K % 16 == 0, 16B-aligned rows (true for all call sites).
// ---------------------------------------------------------------------------
template<int BN, bool TRANSB, int EPI>
__global__ void __launch_bounds__(256)
gemm_tc(const float* __restrict__ A, int lda, long long sAo, long long sAi,
        const float* __restrict__ B, int ldb, long long sBo, long long sBi,
        const float* __restrict__ bias,
        float* __restrict__ C, int ldc, long long sCo, long long sCi,
        const float* __restrict__ res, int ldr,
        int Mrows, int Ncols, int K, int Hdiv,
        float scale, const float* __restrict__ qpos, long long sQ,
        int Mctx, int qposN)
{
    constexpr int NT = BN / 32;           // n-tiles per warp (8-wide each)
    const int z = blockIdx.z;
    const int zo = z / Hdiv, zi = z % Hdiv;
    A += (long long)zo * sAo + (long long)zi * sAi;
    B += (long long)zo * sBo + (long long)zi * sBi;
    C += (long long)zo * sCo + (long long)zi * sCi;
    const float* qp = (EPI == 3) ? (qpos + (long long)z * sQ) : nullptr;

    __shared__ uint32_t Ahi[128][12];
    __shared__ uint32_t Alo[128][12];
    __shared__ float    Bs[16][BN + 4];

    const int tid  = threadIdx.x;
    const int lane = tid & 31;
    const int warp = tid >> 5;
    const int g    = lane >> 2;           // 0..7
    const int t4   = lane & 3;            // 0..3
    const int warpM = warp & 1;           // 0..1
    const int warpN = warp >> 1;          // 0..3
    const int rw = warpM * 64;
    const int cw = warpN * (BN / 4);
    const int r0 = blockIdx.y * 128;
    const int c0 = blockIdx.x * BN;

    float acc[4][NT][4];
    #pragma unroll
    for (int mt = 0; mt < 4; mt++)
        #pragma unroll
        for (int nt = 0; nt < NT; nt++)
            #pragma unroll
            for (int i = 0; i < 4; i++) acc[mt][nt][i] = 0.f;

    const int rowa = tid >> 2;            // 0..63
    const int kqa  = tid & 3;             // 0..3 (k-quad)

    for (int k0 = 0; k0 < K; k0 += 16) {
        // ---- A tile (128 x 16 fp32) -> packed bf16 hi/lo in smem ----
        #pragma unroll
        for (int rr = 0; rr < 2; rr++) {
            int row = rowa + rr * 64;
            int gm  = r0 + row;
            float4 v = make_float4(0.f, 0.f, 0.f, 0.f);
            if (gm < Mrows)
                v = *reinterpret_cast<const float4*>(A + (long long)gm * lda + k0 + kqa * 4);
            uint32_t h0 = pack_hi(v.x, v.y), h1 = pack_hi(v.z, v.w);
            uint32_t l0 = pack_lo(v.x, v.y), l1 = pack_lo(v.z, v.w);
            *reinterpret_cast<uint2*>(&Ahi[row][kqa * 2]) = make_uint2(h0, h1);
            *reinterpret_cast<uint2*>(&Alo[row][kqa * 2]) = make_uint2(l0, l1);
        }
        // ---- B tile (16 x BN fp32) ----
        if (!TRANSB) {
            int kk = tid >> 4;            // 0..15
            int q  = tid & 15;
            #pragma unroll
            for (int rr = 0; rr < BN / 64; rr++) {
                int n0 = (q + rr * 16) * 4;
                float4 v = make_float4(0.f, 0.f, 0.f, 0.f);
                if (c0 + n0 < Ncols)
                    v = *reinterpret_cast<const float4*>(B + (long long)(k0 + kk) * ldb + c0 + n0);
                *reinterpret_cast<float4*>(&Bs[kk][n0]) = v;
            }
        } else {
            int colb = tid >> 2;          // 0..63
            int kq   = tid & 3;
            #pragma unroll
            for (int rr = 0; rr < BN / 64; rr++) {
                int col = colb + rr * 64;
                float4 v = make_float4(0.f, 0.f, 0.f, 0.f);
                if (c0 + col < Ncols)
                    v = *reinterpret_cast<const float4*>(B + (long long)(c0 + col) * ldb + k0 + kq * 4);
                Bs[kq * 4 + 0][col] = v.x;
                Bs[kq * 4 + 1][col] = v.y;
                Bs[kq * 4 + 2][col] = v.z;
                Bs[kq * 4 + 3][col] = v.w;
            }
        }
        __syncthreads();

        // ---- fragments + mma ----
        uint32_t ah[4][4], al[4][4];
        #pragma unroll
        for (int mt = 0; mt < 4; mt++) {
            int rb = rw + mt * 16 + g;
            ah[mt][0] = Ahi[rb][t4];         al[mt][0] = Alo[rb][t4];
            ah[mt][1] = Ahi[rb + 8][t4];     al[mt][1] = Alo[rb + 8][t4];
            ah[mt][2] = Ahi[rb][t4 + 4];     al[mt][2] = Alo[rb][t4 + 4];
            ah[mt][3] = Ahi[rb + 8][t4 + 4]; al[mt][3] = Alo[rb + 8][t4 + 4];
        }
        #pragma unroll
        for (int nt = 0; nt < NT; nt++) {
            int cc = cw + nt * 8 + g;
            uint32_t bh0, bl0, bh1, bl1;
            split_pair(Bs[2 * t4][cc],     Bs[2 * t4 + 1][cc], bh0, bl0);
            split_pair(Bs[2 * t4 + 8][cc], Bs[2 * t4 + 9][cc], bh1, bl1);
            #pragma unroll
            for (int mt = 0; mt < 4; mt++) {
                mma_bf16(acc[mt][nt], ah[mt][0], ah[mt][1], ah[mt][2], ah[mt][3], bh0, bh1);
                mma_bf16(acc[mt][nt], ah[mt][0], ah[mt][1], ah[mt][2], ah[mt][3], bl0, bl1);
                mma_bf16(acc[mt][nt], al[mt][0], al[mt][1], al[mt][2], al[mt][3], bh0, bh1);
            }
        }
        __syncthreads();
    }

    // ---- epilogue ----
    #pragma unroll
    for (int mt = 0; mt < 4; mt++) {
        #pragma unroll
        for (int nt = 0; nt < NT; nt++) {
            int rbase = r0 + rw + mt * 16 + g;
            int cbase = c0 + cw + nt * 8 + 2 * t4;
            #pragma unroll
            for (int e = 0; e < 4; e++) {
                int r = rbase + (e >> 1) * 8;
                int c = cbase + (e & 1);
                if (r >= Mrows || c >= Ncols) continue;
                float v = acc[mt][nt][e];
                if (EPI == 3) {
                    v *= scale;
                    if (c > Mctx + r) {
                        v = -1e30f;                       // causal mask
                    } else if (c >= Mctx) {
                        v += scale * qp[(long long)r * qposN + (qposN - 1 - r + c - Mctx)];
                    }
                } else {
                    if (bias) v += bias[c];
                    if (EPI == 1) v += res[(long long)r * ldr + c];
                    if (EPI == 2) v = 0.5f * v * (1.0f + erff(v * 0.70710678118654752f));
                }
                C[(long long)r * ldc + c] = v;
            }
        }
    }
}

// ---------------------------------------------------------------------------
// Small kernels
// ---------------------------------------------------------------------------
__global__ void pe_kernel(float* __restrict__ pe)
{
    int jj = blockIdx.x;
    double t = (double)(N_ - 1 - jj);
    for (int m = threadIdx.x; m < D_ / 2; m += blockDim.x) {
        double inv = exp(-((2.0 * m) / (double)D_) * log(10000.0));
        double a = t * inv;
        pe[(size_t)jj * D_ + m]            = (float)sin(a);
        pe[(size_t)jj * D_ + D_ / 2 + m]   = (float)cos(a);
    }
}

__global__ void init_aux_kernel() { g_aux[0] = 0.0f; }

__global__ void embed_kernel(const int* __restrict__ x,
                             const float* __restrict__ emb,
                             float* __restrict__ h)
{
    int idx = blockIdx.x;                 // b*N + n
    int tok = x[idx];
    const float* src = emb + (size_t)tok * D_;
    float* dst = h + (size_t)idx * D_;
    for (int i = threadIdx.x; i < D_; i += blockDim.x) dst[i] = src[i];
}

__global__ void layernorm_kernel(const float* __restrict__ in,
                                 const float* __restrict__ g,
                                 const float* __restrict__ bb,
                                 float* __restrict__ out)
{
    size_t row = blockIdx.x;
    const float* p = in + row * D_;
    float s = 0.f, s2 = 0.f;
    for (int i = threadIdx.x; i < D_; i += 256) { float v = p[i]; s += v; s2 += v * v; }
    __shared__ float sh1[256], sh2[256];
    sh1[threadIdx.x] = s; sh2[threadIdx.x] = s2;
    __syncthreads();
    for (int o = 128; o > 0; o >>= 1) {
        if (threadIdx.x < o) { sh1[threadIdx.x] += sh1[threadIdx.x + o];
                               sh2[threadIdx.x] += sh2[threadIdx.x + o]; }
        __syncthreads();
    }
    float mu  = sh1[0] * (1.0f / D_);
    float var = sh2[0] * (1.0f / D_) - mu * mu;
    float inv = rsqrtf(var + 1e-5f);
    for (int i = threadIdx.x; i < D_; i += 256)
        out[row * D_ + i] = (p[i] - mu) * inv * g[i] + bb[i];
}

__global__ void expire_kernel(const float* __restrict__ mem,     // (B, M, D)
                              const int*   __restrict__ times,   // (B, M)
                              const float* __restrict__ Wexp,    // (D,)
                              const float* __restrict__ bexp)    // scalar
{
    int j = blockIdx.x;
    int b = blockIdx.y;
    if (j >= M_) {
        if (threadIdx.x == 0) g_emask[(size_t)b * MN_ + j] = 1.0f;
        return;
    }
    const float* row = mem + ((size_t)b * M_ + j) * D_;
    float s = 0.f;
    for (int i = threadIdx.x; i < D_; i += 256) s += row[i] * Wexp[i];
    __shared__ float sh[256];
    sh[threadIdx.x] = s;
    __syncthreads();
    for (int o = 128; o > 0; o >>= 1) {
        if (threadIdx.x < o) sh[threadIdx.x] += sh[threadIdx.x + o];
        __syncthreads();
    }
    if (threadIdx.x == 0) {
        float e  = (1.0f / (1.0f + expf(-(sh[0] + bexp[0])))) * 2048.0f;
        float r  = e - (float)times[(size_t)b * M_ + j];
        float em = fminf(fmaxf(r * (1.0f / 128.0f) + 1.0f, 0.0f), 1.0f);
        g_emask[(size_t)b * MN_ + j] = em;
        g_auxbuf[(size_t)b * M_ + j] = (em > 0.0f && em < 1.0f) ? e : 0.0f;
    }
}

__global__ void aux_reduce_kernel()
{
    float s = 0.f;
    for (int i = threadIdx.x; i < B_ * M_; i += 256) s += g_auxbuf[i];
    __shared__ float sh[256];
    sh[threadIdx.x] = s;
    __syncthreads();
    for (int o = 128; o > 0; o >>= 1) {
        if (threadIdx.x < o) sh[threadIdx.x] += sh[threadIdx.x + o];
        __syncthreads();
    }
    if (threadIdx.x == 0) g_aux[0] += sh[0] * (1.0f / 1024.0f) * 1e-6f;
}

// Row softmax over MN_ entries (single pass, register resident),
// then post-softmax emask multiply
__global__ void __launch_bounds__(256) softmax_kernel()
{
    size_t row = blockIdx.x;                 // (b*H + h)*N + i
    int b = (int)(row / ((size_t)H_ * N_));
    float* p = g_dots + row * (size_t)MN_;
    const float* em = g_emask + (size_t)b * MN_;
    __shared__ float sh[256];
    const int tid = threadIdx.x;

    float vals[MN_ / 256];
    float m = -1e30f;
    #pragma unroll
    for (int jj = 0; jj < MN_ / 256; jj++) {
        vals[jj] = p[jj * 256 + tid];
        m = fmaxf(m, vals[jj]);
    }
    sh[tid] = m;
    __syncthreads();
    for (int o = 128; o > 0; o >>= 1) {
        if (tid < o) sh[tid] = fmaxf(sh[tid], sh[tid + o]);
        __syncthreads();
    }
    m = sh[0];
    __syncthreads();

    float s = 0.f;
    #pragma unroll
    for (int jj = 0; jj < MN_ / 256; jj++) {
        vals[jj] = __expf(vals[jj] - m);
        s += vals[jj];
    }
    sh[tid] = s;
    __syncthreads();
    for (int o = 128; o > 0; o >>= 1) {
        if (tid < o) sh[tid] += sh[tid + o];
        __syncthreads();
    }
    float inv = 1.0f / sh[0];
    #pragma unroll
    for (int jj = 0; jj < MN_ / 256; jj++)
        p[jj * 256 + tid] = vals[jj] * inv * em[jj * 256 + tid];
}

__global__ void write_aux_kernel(float* __restrict__ out, int out_size)
{
    const long long nlog = (long long)B_ * N_ * V_;
    if (out_size > nlog) out[nlog] = g_aux[0];
}

// ---------------------------------------------------------------------------
// Host orchestration
// ---------------------------------------------------------------------------
static inline dim3 gemm_grid(int Mrows, int Ncols, int z, int bn)
{
    return dim3((Ncols + bn - 1) / bn, (Mrows + 127) / 128, z);
}

extern "C" void kernel_launch(void* const* d_in, const int* in_sizes, int n_in,
                              void* d_out, int out_size)
{
    const int*   x    = (const int*)  d_in[0];
    const float* mems = (const float*)d_in[1];
    const int*   times= (const int*)  d_in[2];
    const float* emb  = (const float*)d_in[3];
    const float* Wq   = (const float*)d_in[4];
    const float* bq   = (const float*)d_in[5];
    const float* Wkv  = (const float*)d_in[6];
    const float* bkv  = (const float*)d_in[7];
    const float* Wo   = (const float*)d_in[8];
    const float* bo   = (const float*)d_in[9];
    const float* Wpos = (const float*)d_in[10];
    const float* bpos = (const float*)d_in[11];
    const float* Wexp = (const float*)d_in[12];
    const float* bexp = (const float*)d_in[13];
    const float* ln1g = (const float*)d_in[14];
    const float* ln1b = (const float*)d_in[15];
    const float* ln2g = (const float*)d_in[16];
    const float* ln2b = (const float*)d_in[17];
    const float* Wff1 = (const float*)d_in[18];
    const float* bff1 = (const float*)d_in[19];
    const float* Wff2 = (const float*)d_in[20];
    const float* bff2 = (const float*)d_in[21];
    const float* Wlog = (const float*)d_in[22];
    const float* blog = (const float*)d_in[23];
    float* out = (float*)d_out;

    float *h, *xn, *q, *ao, *kv, *pe, *pos, *qpos, *dots, *f1;
    cudaGetSymbolAddress((void**)&h,    g_h);
    cudaGetSymbolAddress((void**)&xn,   g_xn);
    cudaGetSymbolAddress((void**)&q,    g_q);
    cudaGetSymbolAddress((void**)&ao,   g_ao);
    cudaGetSymbolAddress((void**)&kv,   g_kv);
    cudaGetSymbolAddress((void**)&pe,   g_pe);
    cudaGetSymbolAddress((void**)&pos,  g_pos);
    cudaGetSymbolAddress((void**)&qpos, g_qpos);
    cudaGetSymbolAddress((void**)&dots, g_dots);
    cudaGetSymbolAddress((void**)&f1,   g_f1);

    pe_kernel<<<N_, 512>>>(pe);
    init_aux_kernel<<<1, 1>>>();
    embed_kernel<<<B_ * N_, 256>>>(x, emb, h);

    const long long sKVb = (long long)MN_ * 2 * D_;   // kv batch stride
    const long long sDb  = (long long)H_ * N_ * MN_;  // dots batch(b) stride
    const long long sDh  = (long long)N_ * MN_;       // dots head stride

    for (int l = 0; l < L_; l++) {
        // --- expiration mask + aux ---
        expire_kernel<<<dim3(MN_, B_), 256>>>(mems + (size_t)l * B_ * M_ * D_,
                                              times + (size_t)l * B_ * M_,
                                              Wexp + (size_t)l * D_,
                                              bexp + l);
        aux_reduce_kernel<<<1, 256>>>();

        // --- xn = LN1(h) ---
        layernorm_kernel<<<B_ * N_, 256>>>(h, ln1g + (size_t)l * D_, ln1b + (size_t)l * D_, xn);

        // --- q = xn @ Wq + bq  (2048 x 1024, K=1024) ---
        gemm_tc<128, false, 0><<<gemm_grid(B_ * N_, D_, 1, 128), 256>>>(
            xn, D_, 0, 0, Wq + (size_t)l * D_ * D_, D_, 0, 0, bq + (size_t)l * D_,
            q, D_, 0, 0, nullptr, 0, B_ * N_, D_, D_, 1, 0.f, nullptr, 0, 0, 0);

        // --- kv[:, :M] = mem @ Wkv + bkv  (per batch) ---
        gemm_tc<128, false, 0><<<gemm_grid(M_, 2 * D_, B_, 128), 256>>>(
            mems + (size_t)l * B_ * M_ * D_, D_, (long long)M_ * D_, 0,
            Wkv + (size_t)l * D_ * 2 * D_, 2 * D_, 0, 0, bkv + (size_t)l * 2 * D_,
            kv, 2 * D_, sKVb, 0, nullptr, 0, M_, 2 * D_, D_, 1, 0.f, nullptr, 0, 0, 0);

        // --- kv[:, M:] = xn @ Wkv + bkv  (per batch) ---
        gemm_tc<128, false, 0><<<gemm_grid(N_, 2 * D_, B_, 128), 256>>>(
            xn, D_, (long long)N_ * D_, 0,
            Wkv + (size_t)l * D_ * 2 * D_, 2 * D_, 0, 0, bkv + (size_t)l * 2 * D_,
            kv + (size_t)M_ * 2 * D_, 2 * D_, sKVb, 0, nullptr, 0,
            N_, 2 * D_, D_, 1, 0.f, nullptr, 0, 0, 0);

        // --- pos = pe @ Wpos + bpos  (1024 x 64, K=1024) ---
        gemm_tc<64, false, 0><<<gemm_grid(N_, DH_, 1, 64), 256>>>(
            pe, D_, 0, 0, Wpos + (size_t)l * D_ * DH_, DH_, 0, 0, bpos + (size_t)l * DH_,
            pos, DH_, 0, 0, nullptr, 0, N_, DH_, D_, 1, 0.f, nullptr, 0, 0, 0);

        // --- qpos[b,h] = q[b,:,h,:] @ pos^T  (1024 x 1024, K=64), 32 batches ---
        gemm_tc<128, true, 0><<<gemm_grid(N_, N_, B_ * H_, 128), 256>>>(
            q, D_, (long long)N_ * D_, DH_,
            pos, DH_, 0, 0, nullptr,
            qpos, N_, (long long)H_ * N_ * N_, (long long)N_ * N_, nullptr, 0,
            N_, N_, DH_, H_, 0.f, nullptr, 0, 0, 0);

        // --- dots = SCALE*(q k^T) + rel-shift(pos) + causal mask ---
        gemm_tc<128, true, 3><<<gemm_grid(N_, MN_, B_ * H_, 128), 256>>>(
            q, D_, (long long)N_ * D_, DH_,
            kv, 2 * D_, sKVb, DH_, nullptr,
            dots, MN_, sDb, sDh, nullptr, 0,
            N_, MN_, DH_, H_, SCALE_, qpos, (long long)N_ * N_, M_, N_);

        // --- softmax rows, post-multiply emask ---
        softmax_kernel<<<B_ * H_ * N_, 256>>>();

        // --- ao[b,:,h,:] = attn @ v  (1024 x 64, K=3072), 32 batches ---
        gemm_tc<64, false, 0><<<gemm_grid(N_, DH_, B_ * H_, 64), 256>>>(
            dots, MN_, sDb, sDh,
            kv + D_, 2 * D_, sKVb, DH_, nullptr,
            ao, D_, (long long)N_ * D_, DH_, nullptr, 0,
            N_, DH_, MN_, H_, 0.f, nullptr, 0, 0, 0);

        // --- h = ao @ Wo + bo + h ---
        gemm_tc<128, false, 1><<<gemm_grid(B_ * N_, D_, 1, 128), 256>>>(
            ao, D_, 0, 0, Wo + (size_t)l * D_ * D_, D_, 0, 0, bo + (size_t)l * D_,
            h, D_, 0, 0, h, D_, B_ * N_, D_, D_, 1, 0.f, nullptr, 0, 0, 0);

        // --- xn = LN2(h) ---
        layernorm_kernel<<<B_ * N_, 256>>>(h, ln2g + (size_t)l * D_, ln2b + (size_t)l * D_, xn);

        // --- f1 = gelu(xn @ Wff1 + bff1)  (2048 x 4096, K=1024) ---
        gemm_tc<128, false, 2><<<gemm_grid(B_ * N_, FF_, 1, 128), 256>>>(
            xn, D_, 0, 0, Wff1 + (size_t)l * D_ * FF_, FF_, 0, 0, bff1 + (size_t)l * FF_,
            f1, FF_, 0, 0, nullptr, 0, B_ * N_, FF_, D_, 1, 0.f, nullptr, 0, 0, 0);

        // --- h = f1 @ Wff2 + bff2 + h  (2048 x 1024, K=4096) ---
        gemm_tc<128, false, 1><<<gemm_grid(B_ * N_, D_, 1, 128), 256>>>(
            f1, FF_, 0, 0, Wff2 + (size_t)l * FF_ * D_, D_, 0, 0, bff2 + (size_t)l * D_,
            h, D_, 0, 0, h, D_, B_ * N_, D_, FF_, 1, 0.f, nullptr, 0, 0, 0);
    }

    // --- logits = h @ Wlog + blog  (2048 x 32000, K=1024) -> d_out ---
    gemm_tc<128, false, 0><<<gemm_grid(B_ * N_, V_, 1, 128), 256>>>(
        h, D_, 0, 0, Wlog, V_, 0, 0, blog,
        out, V_, 0, 0, nullptr, 0, B_ * N_, V_, D_, 1, 0.f, nullptr, 0, 0, 0);

    write_aux_kernel<<<1, 1>>>(out, out_size);
}